// round 7
// baseline (speedup 1.0000x reference)
#include <cuda_runtime.h>
#include <cstdint>

#define TLEN   8192
#define BATCH  128
#define NS     128
#define EMITN  64
#define NT     288   // 8 compute warps (2-way split-K over 128 states) + 1 relay warp

// ---- packed f32x2 helpers (sm_103a) ----
__device__ __forceinline__ void fma2(unsigned long long& d, unsigned long long a, unsigned long long b) {
    asm("fma.rn.f32x2 %0, %1, %2, %0;" : "+l"(d) : "l"(a), "l"(b));
}
__device__ __forceinline__ unsigned long long mul2(unsigned long long a, unsigned long long b) {
    unsigned long long d;
    asm("mul.rn.f32x2 %0, %1, %2;" : "=l"(d) : "l"(a), "l"(b));
    return d;
}
__device__ __forceinline__ unsigned long long padd(unsigned long long a, unsigned long long b) {
    unsigned long long d;
    asm("add.rn.f32x2 %0, %1, %2;" : "=l"(d) : "l"(a), "l"(b));
    return d;
}
__device__ __forceinline__ unsigned long long pk(float lo, float hi) {
    unsigned long long r;
    asm("mov.b64 %0, {%1, %2};" : "=l"(r) : "f"(lo), "f"(hi));
    return r;
}
__device__ __forceinline__ float hsum2(unsigned long long v) {
    float lo, hi;
    asm("mov.b64 {%0, %1}, %2;" : "=f"(lo), "=f"(hi) : "l"(v));
    return lo + hi;
}

__global__ __launch_bounds__(NT, 1)
void hmm_forward_kernel(const float* __restrict__ inputs,
                        const float* __restrict__ Ivec,
                        const float* __restrict__ Amat,
                        const float* __restrict__ Bmat,
                        float* __restrict__ out)
{
    __shared__ float Bsh[EMITN * NS];              // 32 KB
    __shared__ unsigned char obs_sm[TLEN];         // 8 KB
    __shared__ __align__(16) float ubuf[2][NS];    // double-buffered v_t
    __shared__ __align__(16) float partB[NS];      // h=1 half-dot partials
    __shared__ __align__(16) float zs1[2][8];      // relay stage-1 partials
    __shared__ float sc_sm[2];                     // exact pow2 scale
    __shared__ __align__(16) float znext[4];
    __shared__ __align__(16) float zvs[4];
    __shared__ int stot_sm;

    const int tid  = threadIdx.x;
    const int lane = tid & 31;
    const int w    = tid >> 5;
    const int b    = blockIdx.x;
    const bool isCompute = (tid < 256);
    const int s    = tid & 127;          // state
    const int h    = (tid >> 7) & 1;     // k-half: k in [64h, 64h+64)

    // ---- prologue: B into smem ----
    for (int i = tid; i < EMITN * NS; i += NT) Bsh[i] = Bmat[i];

    // ---- prologue: one-hot -> obs index (exact dot with iota) ----
    {
        const float* xin = inputs + (size_t)b * TLEN * EMITN;
        for (int t = tid; t < TLEN; t += NT) {
            const float4* r = (const float4*)(xin + (size_t)t * EMITN);
            float idx = 0.0f;
            #pragma unroll
            for (int j = 0; j < 16; j++) {
                float4 v = r[j];
                idx = fmaf((float)(4 * j + 0), v.x, idx);
                idx = fmaf((float)(4 * j + 1), v.y, idx);
                idx = fmaf((float)(4 * j + 2), v.z, idx);
                idx = fmaf((float)(4 * j + 3), v.w, idx);
            }
            obs_sm[t] = (unsigned char)__float2int_rn(idx);
        }
    }

    // ---- prologue: half A column -> 32 packed f32x2 (64 regs) ----
    unsigned long long Ar[32];
    if (isCompute) {
        const int k0 = 64 * h;
        #pragma unroll
        for (int j = 0; j < 32; j++) {
            float a0 = Amat[(k0 + 2 * j) * NS + s];
            float a1 = Amat[(k0 + 2 * j + 1) * NS + s];
            Ar[j] = pk(a0, a1);
        }
    }
    float Ival = (tid < 128) ? Ivec[s] : 0.0f;
    __syncthreads();

    // ---- init: v0 = E0*I; prime relay ----
    if (tid < 128) {
        int o0 = obs_sm[0];
        ubuf[0][s] = Bsh[o0 * NS + s] * Ival;
    } else if (tid >= 256) {
        int l = tid - 256;
        if (l < 8) { zs1[0][l] = 0.125f; zs1[1][l] = 0.125f; }   // Z=1 -> e=0
        if (l == 0) { sc_sm[0] = 1.0f; sc_sm[1] = 1.0f; }
    }
    __syncthreads();

    int   Stot  = 0;                  // (valid on tid==256)
    float Elast = 0.f, Rlast = 0.f, vlast = 0.f;

    // ---- main recurrence: lean 2-phase, 2 barriers ----
    for (int t = 1; t < TLEN; t++) {
        const int pb = (t - 1) & 1, cb = t & 1;
        float E = 0.f, Escf = 0.f, pown = 0.f;

        if (isCompute) {
            if (h == 0) {                       // prefetch emission * scale
                int o = obs_sm[t];
                float scf = sc_sm[pb];
                E = Bsh[o * NS + s];
                Escf = E * scf;
            }
            // half-dot: sum over own 64 k's
            const ulonglong2* up = (const ulonglong2*)ubuf[pb] + 16 * h;
            ulonglong2 c0 = up[0], c1 = up[1], c2 = up[2], c3 = up[3];
            unsigned long long a0 = mul2(c0.x, Ar[0]), a1 = mul2(c0.y, Ar[1]);
            unsigned long long a2 = mul2(c1.x, Ar[2]), a3 = mul2(c1.y, Ar[3]);
            unsigned long long a4 = mul2(c2.x, Ar[4]), a5 = mul2(c2.y, Ar[5]);
            unsigned long long a6 = mul2(c3.x, Ar[6]), a7 = mul2(c3.y, Ar[7]);
            ulonglong2 c4 = up[4], c5 = up[5], c6 = up[6], c7 = up[7];
            fma2(a0, c4.x, Ar[8]);   fma2(a1, c4.y, Ar[9]);
            fma2(a2, c5.x, Ar[10]);  fma2(a3, c5.y, Ar[11]);
            fma2(a4, c6.x, Ar[12]);  fma2(a5, c6.y, Ar[13]);
            fma2(a6, c7.x, Ar[14]);  fma2(a7, c7.y, Ar[15]);
            ulonglong2 c8 = up[8], c9 = up[9], c10 = up[10], c11 = up[11];
            fma2(a0, c8.x,  Ar[16]); fma2(a1, c8.y,  Ar[17]);
            fma2(a2, c9.x,  Ar[18]); fma2(a3, c9.y,  Ar[19]);
            fma2(a4, c10.x, Ar[20]); fma2(a5, c10.y, Ar[21]);
            fma2(a6, c11.x, Ar[22]); fma2(a7, c11.y, Ar[23]);
            ulonglong2 c12 = up[12], c13 = up[13], c14 = up[14], c15 = up[15];
            fma2(a0, c12.x, Ar[24]); fma2(a1, c12.y, Ar[25]);
            fma2(a2, c13.x, Ar[26]); fma2(a3, c13.y, Ar[27]);
            fma2(a4, c14.x, Ar[28]); fma2(a5, c14.y, Ar[29]);
            fma2(a6, c15.x, Ar[30]); fma2(a7, c15.y, Ar[31]);

            unsigned long long pp = padd(padd(padd(a0, a1), padd(a2, a3)),
                                         padd(padd(a4, a5), padd(a6, a7)));
            float pf = hsum2(pp);
            if (h) partB[s] = pf;               // STS.32, conflict-free
            else   pown = pf;
        } else {
            // ---- relay warp: pipelined stale-Z pow2 controller (delay-3, gain 1/4) ----
            float4 za, zb;
            if (lane == 0) {
                za = *(const float4*)&zs1[pb][0];
                zb = *(const float4*)&zs1[pb][4];
            }
            float4 a = ((const float4*)ubuf[pb])[lane];
            float zsum = (a.x + a.y) + (a.z + a.w);
            zsum += __shfl_xor_sync(0xffffffffu, zsum, 1);
            zsum += __shfl_xor_sync(0xffffffffu, zsum, 2);
            if ((lane & 3) == 0) zs1[cb][lane >> 2] = zsum;
            if (lane == 0) {
                float Z = ((za.x + za.y) + (za.z + za.w)) + ((zb.x + zb.y) + (zb.z + zb.w));
                int e = ((((__float_as_int(Z) >> 23) & 255) - 127) >> 2);
                if (t < TLEN - 1) Stot += e;
                sc_sm[cb] = __int_as_float((127 - e) << 23);   // 2^{-e}, exact
            }
        }
        __syncthreads();                        // BAR1: partB / relay outputs ready

        if (tid < 128) {                        // minimal combine: h=0 only
            float R = pown + partB[s];
            float v = Escf * R;
            ubuf[cb][s] = v;
            Elast = E; Rlast = R; vlast = v;
        }
        __syncthreads();                        // BAR2: v_t published
    }

    // ---- epilogue ----
    if (tid == 256) stot_sm = Stot;
    if (tid < 128) {
        float rr = Rlast, vv = vlast;
        #pragma unroll
        for (int off = 16; off > 0; off >>= 1) {
            rr += __shfl_xor_sync(0xffffffffu, rr, off);
            vv += __shfl_xor_sync(0xffffffffu, vv, off);
        }
        if (lane == 0) { znext[w] = rr; zvs[w] = vv; }
    }
    __syncthreads();

    if (tid < 128) {
        float4 zn = *(const float4*)znext;
        float SR = (zn.x + zn.y) + (zn.z + zn.w);      // = sum(v_{T-2}) (A rows sum to 1)
        out[b * NS + s] = Elast * Rlast / SR;          // alpha_f (pow2 factors cancel)
    }
    if (tid == 0) {
        float4 zv = *(const float4*)zvs;
        float SV = (zv.x + zv.y) + (zv.z + zv.w);      // sum(v_{T-1})
        double ll = log((double)SV) + (double)stot_sm * 0.6931471805599453;
        out[BATCH * NS + b] = (float)ll;               // loglik
    }
}

extern "C" void kernel_launch(void* const* d_in, const int* in_sizes, int n_in,
                              void* d_out, int out_size)
{
    const float* inputs = (const float*)d_in[0];   // [128, 8192, 64]
    const float* Ivec   = (const float*)d_in[1];   // [128]
    const float* Amat   = (const float*)d_in[2];   // [128, 128]
    const float* Bmat   = (const float*)d_in[3];   // [64, 128]
    float* out = (float*)d_out;                    // alpha_f [128,128] ++ loglik [128]

    hmm_forward_kernel<<<BATCH, NT>>>(inputs, Ivec, Amat, Bmat, out);
}

// round 8
// speedup vs baseline: 1.0161x; 1.0161x over previous
#include <cuda_runtime.h>
#include <cstdint>

#define TLEN   8192
#define BATCH  128
#define NS     128
#define EMITN  64
#define NT     288   // 8 compute warps (16 states x 2 k-halves each) + 1 relay warp

// ---- packed f32x2 helpers (sm_103a) ----
__device__ __forceinline__ void fma2(unsigned long long& d, unsigned long long a, unsigned long long b) {
    asm("fma.rn.f32x2 %0, %1, %2, %0;" : "+l"(d) : "l"(a), "l"(b));
}
__device__ __forceinline__ unsigned long long mul2(unsigned long long a, unsigned long long b) {
    unsigned long long d;
    asm("mul.rn.f32x2 %0, %1, %2;" : "=l"(d) : "l"(a), "l"(b));
    return d;
}
__device__ __forceinline__ unsigned long long padd(unsigned long long a, unsigned long long b) {
    unsigned long long d;
    asm("add.rn.f32x2 %0, %1, %2;" : "=l"(d) : "l"(a), "l"(b));
    return d;
}
__device__ __forceinline__ unsigned long long pk(float lo, float hi) {
    unsigned long long r;
    asm("mov.b64 %0, {%1, %2};" : "=l"(r) : "f"(lo), "f"(hi));
    return r;
}
__device__ __forceinline__ float hsum2(unsigned long long v) {
    float lo, hi;
    asm("mov.b64 {%0, %1}, %2;" : "=f"(lo), "=f"(hi) : "l"(v));
    return lo + hi;
}

__global__ __launch_bounds__(NT, 1)
void hmm_forward_kernel(const float* __restrict__ inputs,
                        const float* __restrict__ Ivec,
                        const float* __restrict__ Amat,
                        const float* __restrict__ Bmat,
                        float* __restrict__ out)
{
    __shared__ float Bsh[EMITN * NS];              // 32 KB
    __shared__ unsigned char obs_sm[TLEN];         // 8 KB
    __shared__ __align__(16) float ubuf[2][NS];    // double-buffered v_t
    __shared__ __align__(16) float zs1[2][8];      // relay stage-1 partials
    __shared__ float sc_sm[2];                     // exact pow2 scale (relay output)
    __shared__ __align__(16) float znext[8];       // epilogue: per-warp sum R
    __shared__ __align__(16) float zvs[8];         // epilogue: per-warp sum v
    __shared__ int stot_sm;

    const int tid  = threadIdx.x;
    const int lane = tid & 31;
    const int w    = tid >> 5;          // 0..8
    const int b    = blockIdx.x;
    const bool isCompute = (tid < 256);
    const int s    = (w << 4) | (lane & 15);   // state (compute warps)
    const int h    = lane >> 4;                // k-half: k in [64h, 64h+64)

    // ---- prologue: B into smem ----
    for (int i = tid; i < EMITN * NS; i += NT) Bsh[i] = Bmat[i];

    // ---- prologue: one-hot -> obs index (exact dot with iota) ----
    {
        const float* xin = inputs + (size_t)b * TLEN * EMITN;
        for (int t = tid; t < TLEN; t += NT) {
            const float4* r = (const float4*)(xin + (size_t)t * EMITN);
            float idx = 0.0f;
            #pragma unroll
            for (int j = 0; j < 16; j++) {
                float4 v = r[j];
                idx = fmaf((float)(4 * j + 0), v.x, idx);
                idx = fmaf((float)(4 * j + 1), v.y, idx);
                idx = fmaf((float)(4 * j + 2), v.z, idx);
                idx = fmaf((float)(4 * j + 3), v.w, idx);
            }
            obs_sm[t] = (unsigned char)__float2int_rn(idx);
        }
    }

    // ---- prologue: half A column -> 32 packed f32x2 (64 regs) ----
    unsigned long long Ar[32];
    if (isCompute) {
        const int k0 = 64 * h;
        #pragma unroll
        for (int j = 0; j < 32; j++) {
            float a0 = Amat[(k0 + 2 * j) * NS + s];
            float a1 = Amat[(k0 + 2 * j + 1) * NS + s];
            Ar[j] = pk(a0, a1);
        }
    }
    __syncthreads();

    // ---- init: v0 = E0*I (h=0 lanes cover all 128 states); prime relay ----
    if (isCompute) {
        if (h == 0) {
            int o0 = obs_sm[0];
            ubuf[0][s] = Bsh[o0 * NS + s] * Ivec[s];
        }
    } else {
        if (lane < 8) { zs1[0][lane] = 0.125f; zs1[1][lane] = 0.125f; }  // Z=1 -> e=0
        if (lane == 0) { sc_sm[0] = 1.0f; sc_sm[1] = 1.0f; }
    }
    __syncthreads();

    int   Stot  = 0;                  // (valid on tid==256)
    float Elast = 0.f, Rlast = 0.f, vlast = 0.f;

    // ---- main recurrence: ONE barrier per step, shuffle-based split-K ----
    for (int t = 1; t < TLEN; t++) {
        const int pb = (t - 1) & 1, cb = t & 1;

        if (isCompute) {
            // prefetch emission * scale (independent of FMA chain)
            int o = obs_sm[t];
            float scf = sc_sm[pb];
            float E = Bsh[o * NS + s];
            float Escf = E * scf;

            // half-dot over own 64 k's (16 LDS.128, 8 acc chains)
            const ulonglong2* up = (const ulonglong2*)ubuf[pb] + 16 * h;
            ulonglong2 c0 = up[0], c1 = up[1], c2 = up[2], c3 = up[3];
            unsigned long long a0 = mul2(c0.x, Ar[0]), a1 = mul2(c0.y, Ar[1]);
            unsigned long long a2 = mul2(c1.x, Ar[2]), a3 = mul2(c1.y, Ar[3]);
            unsigned long long a4 = mul2(c2.x, Ar[4]), a5 = mul2(c2.y, Ar[5]);
            unsigned long long a6 = mul2(c3.x, Ar[6]), a7 = mul2(c3.y, Ar[7]);
            ulonglong2 c4 = up[4], c5 = up[5], c6 = up[6], c7 = up[7];
            fma2(a0, c4.x, Ar[8]);   fma2(a1, c4.y, Ar[9]);
            fma2(a2, c5.x, Ar[10]);  fma2(a3, c5.y, Ar[11]);
            fma2(a4, c6.x, Ar[12]);  fma2(a5, c6.y, Ar[13]);
            fma2(a6, c7.x, Ar[14]);  fma2(a7, c7.y, Ar[15]);
            ulonglong2 c8 = up[8], c9 = up[9], c10 = up[10], c11 = up[11];
            fma2(a0, c8.x,  Ar[16]); fma2(a1, c8.y,  Ar[17]);
            fma2(a2, c9.x,  Ar[18]); fma2(a3, c9.y,  Ar[19]);
            fma2(a4, c10.x, Ar[20]); fma2(a5, c10.y, Ar[21]);
            fma2(a6, c11.x, Ar[22]); fma2(a7, c11.y, Ar[23]);
            ulonglong2 c12 = up[12], c13 = up[13], c14 = up[14], c15 = up[15];
            fma2(a0, c12.x, Ar[24]); fma2(a1, c12.y, Ar[25]);
            fma2(a2, c13.x, Ar[26]); fma2(a3, c13.y, Ar[27]);
            fma2(a4, c14.x, Ar[28]); fma2(a5, c14.y, Ar[29]);
            fma2(a6, c15.x, Ar[30]); fma2(a7, c15.y, Ar[31]);

            unsigned long long pp = padd(padd(padd(a0, a1), padd(a2, a3)),
                                         padd(padd(a4, a5), padd(a6, a7)));
            float pf = hsum2(pp);

            // exchange half-partials within the warp (lane ^ 16 = same state, other half)
            float pother = __shfl_xor_sync(0xffffffffu, pf, 16);
            float R = pf + pother;                 // bit-identical on both lanes
            float v = Escf * R;
            if (h == 0) ubuf[cb][s] = v;           // STS.32, conflict-free
            Elast = E; Rlast = R; vlast = v;
        } else {
            // ---- relay warp: pipelined stale-Z pow2 controller (delay-3, gain 1/4) ----
            float4 za, zb;
            if (lane == 0) {
                za = *(const float4*)&zs1[pb][0];
                zb = *(const float4*)&zs1[pb][4];
            }
            float4 a = ((const float4*)ubuf[pb])[lane];
            float zsum = (a.x + a.y) + (a.z + a.w);
            zsum += __shfl_xor_sync(0xffffffffu, zsum, 1);
            zsum += __shfl_xor_sync(0xffffffffu, zsum, 2);
            if ((lane & 3) == 0) zs1[cb][lane >> 2] = zsum;
            if (lane == 0) {
                float Z = ((za.x + za.y) + (za.z + za.w)) + ((zb.x + zb.y) + (zb.z + zb.w));
                int e = ((((__float_as_int(Z) >> 23) & 255) - 127) >> 2);
                if (t < TLEN - 1) Stot += e;
                sc_sm[cb] = __int_as_float((127 - e) << 23);   // 2^{-e}, exact
            }
        }
        __syncthreads();   // v_t, zs1, scf all published
    }

    // ---- epilogue ----
    if (tid == 256) stot_sm = Stot;
    if (isCompute) {
        // reduce over the 16 states of this warp (offs 8..1 stay within a half)
        float rr = Rlast, vv = vlast;
        #pragma unroll
        for (int off = 8; off > 0; off >>= 1) {
            rr += __shfl_xor_sync(0xffffffffu, rr, off);
            vv += __shfl_xor_sync(0xffffffffu, vv, off);
        }
        if (lane == 0) { znext[w] = rr; zvs[w] = vv; }
    }
    __syncthreads();

    if (isCompute && h == 0) {
        float4 z0 = *(const float4*)&znext[0];
        float4 z1 = *(const float4*)&znext[4];
        float SR = ((z0.x + z0.y) + (z0.z + z0.w)) + ((z1.x + z1.y) + (z1.z + z1.w));
        out[b * NS + s] = Elast * Rlast / SR;          // alpha_f (pow2 factors cancel)
    }
    if (tid == 0) {
        float4 v0 = *(const float4*)&zvs[0];
        float4 v1 = *(const float4*)&zvs[4];
        float SV = ((v0.x + v0.y) + (v0.z + v0.w)) + ((v1.x + v1.y) + (v1.z + v1.w));
        double ll = log((double)SV) + (double)stot_sm * 0.6931471805599453;
        out[BATCH * NS + b] = (float)ll;               // loglik
    }
}

extern "C" void kernel_launch(void* const* d_in, const int* in_sizes, int n_in,
                              void* d_out, int out_size)
{
    const float* inputs = (const float*)d_in[0];   // [128, 8192, 64]
    const float* Ivec   = (const float*)d_in[1];   // [128]
    const float* Amat   = (const float*)d_in[2];   // [128, 128]
    const float* Bmat   = (const float*)d_in[3];   // [64, 128]
    float* out = (float*)d_out;                    // alpha_f [128,128] ++ loglik [128]

    hmm_forward_kernel<<<BATCH, NT>>>(inputs, Ivec, Amat, Bmat, out);
}